// round 1
// baseline (speedup 1.0000x reference)
#include <cuda_runtime.h>
#include <cuda_bf16.h>
#include <math.h>

// Problem constants
#define BB 2
#define SS 1024
#define HH 1024
#define NHH 16
#define HDD 64
#define SP_C 0.05f
#define EPS_C 1e-5f
#define SCALE_C 0.125f   // 1/sqrt(64)

#define M_TOT (BB*SS)    // 2048

// ---------------- scratch (device globals: no allocations allowed) ----------
__device__ float g_Q[M_TOT*HH];
__device__ float g_K[M_TOT*HH];
__device__ float g_V[M_TOT*HH];
__device__ float g_ctx[M_TOT*HH];
__device__ float g_pre[M_TOT*HH];
__device__ float g_msbh[NHH];
__device__ float g_spec[BB];
__device__ float g_part[BB*16*HH];   // partial column sums of query over seq

// ---------------- tiled fp32 GEMM: C[M,N] = A[M,K] @ W[K,N] + bias (+res) ----
// BM=BN=64, BK=16, 256 threads, 4x4 per thread.
__global__ void sgemm_kernel(const float* __restrict__ A,
                             const float* __restrict__ W,
                             const float* __restrict__ bias,
                             const float* __restrict__ res,
                             float* __restrict__ C,
                             int M, int N, int K)
{
    __shared__ float As[16][68];   // [kk][row], row-stride 68 -> 16B aligned float4
    __shared__ float Bs[16][64];   // [kk][col]

    int tid = threadIdx.x;
    int ty = tid >> 4;             // 0..15 -> row group
    int tx = tid & 15;             // 0..15 -> col group
    int row0 = blockIdx.y * 64;
    int col0 = blockIdx.x * 64;

    const float* Ab = A + (size_t)row0 * K;
    const float* Wb = W + col0;

    float acc[4][4] = {};

    for (int k0 = 0; k0 < K; k0 += 16) {
        #pragma unroll
        for (int i = 0; i < 4; i++) {
            int idx = tid + i * 256;           // 0..1023
            int r = idx >> 4, kk = idx & 15;   // 64x16 tile of A
            As[kk][r] = Ab[(size_t)r * K + k0 + kk];
        }
        #pragma unroll
        for (int i = 0; i < 4; i++) {
            int idx = tid + i * 256;
            int kk = idx >> 6, c = idx & 63;   // 16x64 tile of W
            Bs[kk][c] = Wb[(size_t)(k0 + kk) * N + c];
        }
        __syncthreads();
        #pragma unroll
        for (int kk = 0; kk < 16; kk++) {
            float4 a4 = *(const float4*)&As[kk][ty * 4];
            float4 b4 = *(const float4*)&Bs[kk][tx * 4];
            float av[4] = {a4.x, a4.y, a4.z, a4.w};
            float bv[4] = {b4.x, b4.y, b4.z, b4.w};
            #pragma unroll
            for (int i = 0; i < 4; i++)
                #pragma unroll
                for (int j = 0; j < 4; j++)
                    acc[i][j] += av[i] * bv[j];
        }
        __syncthreads();
    }

    #pragma unroll
    for (int i = 0; i < 4; i++) {
        int r = row0 + ty * 4 + i;
        #pragma unroll
        for (int j = 0; j < 4; j++) {
            int c = col0 + tx * 4 + j;
            float v = acc[i][j] + bias[c];
            if (res) v += res[(size_t)r * N + c];
            C[(size_t)r * N + c] = v;
        }
    }
}

// ---------------- msb per-head mean ----------------
__global__ void msb_kernel(const float* __restrict__ msb)
{
    __shared__ float red[256];
    int h = blockIdx.x, tid = threadIdx.x;
    const float* p = msb + (size_t)h * HDD * HDD;
    float s = 0.f;
    for (int i = tid; i < HDD * HDD; i += 256) s += p[i];
    red[tid] = s;
    __syncthreads();
    for (int off = 128; off > 0; off >>= 1) {
        if (tid < off) red[tid] += red[tid + off];
        __syncthreads();
    }
    if (tid == 0) g_msbh[h] = red[0] * (1.0f / (HDD * HDD));
}

// ---------------- stage 1 of query mean over seq (deterministic tree) -------
__global__ void qmean_part(const float* __restrict__ q)
{
    int b = blockIdx.y, ch = blockIdx.x;     // 16 chunks of 64 rows
    int tid = threadIdx.x;                   // 256
    for (int c = tid; c < HH; c += 256) {
        const float* base = q + ((size_t)b * SS + ch * 64) * HH + c;
        float s = 0.f;
        #pragma unroll 4
        for (int r = 0; r < 64; r++) s += base[(size_t)r * HH];
        g_part[((size_t)b * 16 + ch) * HH + c] = s;
    }
}

// ---------------- spec MLP: per-batch scalar -------------------------------
__global__ void spec_kernel(const float* __restrict__ Ws1, const float* __restrict__ bs1,
                            const float* __restrict__ Ws2, const float* __restrict__ bs2)
{
    __shared__ float sin_[HH];
    __shared__ float h1[HH / 2];
    __shared__ float red[512];
    int b = blockIdx.x, tid = threadIdx.x;   // 512 threads

    for (int c = tid; c < HH; c += 512) {
        float s = 0.f;
        #pragma unroll
        for (int p = 0; p < 16; p++) s += g_part[((size_t)b * 16 + p) * HH + c];
        sin_[c] = s * (1.0f / SS);
    }
    __syncthreads();

    {   // h1 = relu(sin_ @ Ws1 + bs1), Ws1 is [1024,512]
        float s = bs1[tid];
        for (int i = 0; i < HH; i++) s += sin_[i] * Ws1[(size_t)i * 512 + tid];
        h1[tid] = fmaxf(s, 0.f);
    }
    __syncthreads();

    float acc = 0.f;
    for (int c = tid; c < HH; c += 512) {     // Ws2 is [512,1024]
        float s = bs2[c];
        for (int i = 0; i < 512; i++) s += h1[i] * Ws2[(size_t)i * HH + c];
        acc += 1.0f / (1.0f + __expf(-s));
    }
    red[tid] = acc;
    __syncthreads();
    for (int off = 256; off > 0; off >>= 1) {
        if (tid < off) red[tid] += red[tid + off];
        __syncthreads();
    }
    if (tid == 0) g_spec[b] = red[0] * (1.0f / HH);
}

// ---------------- fused flash-style attention -------------------------------
// block = (qtile, head, batch); 256 threads; 64q x 64k tiles; online softmax.
#define ATT_SMEM_FLOATS (3*64*65 + 64*64 + 192)
#define ATT_SMEM_BYTES  (ATT_SMEM_FLOATS * 4)

__global__ void attn_kernel()
{
    extern __shared__ float sm[];
    float* Qs = sm;                 // [q][d] stride 65
    float* Ks = Qs + 64 * 65;       // [k][d] stride 65
    float* Ps = Ks + 64 * 65;       // [q][k] stride 65
    float* Vs = Ps + 64 * 65;       // [k][d] stride 64
    float* mrow = Vs + 64 * 64;
    float* lrow = mrow + 64;
    float* crow = lrow + 64;

    int b = blockIdx.z, h = blockIdx.y, q0 = blockIdx.x << 6;
    int tid = threadIdx.x;
    int ty = tid >> 4, tx = tid & 15;
    int qr = ty << 2, vc = tx << 2;

    const size_t base = ((size_t)b * SS + q0) * HH + h * HDD;
    const float* Qg = g_Q + base;

    for (int idx = tid; idx < 4096; idx += 256) {
        int r = idx >> 6, d = idx & 63;
        Qs[r * 65 + d] = Qg[(size_t)r * HH + d];
    }
    if (tid < 64) { mrow[tid] = -1e30f; lrow[tid] = 0.f; }

    float acc[4][4] = {};
    float mh = g_msbh[h];
    float sp = g_spec[b];

    for (int kt = 0; kt < 16; kt++) {
        __syncthreads();
        const float* Kg = g_K + ((size_t)b * SS + kt * 64) * HH + h * HDD;
        const float* Vg = g_V + ((size_t)b * SS + kt * 64) * HH + h * HDD;
        for (int idx = tid; idx < 4096; idx += 256) {
            int r = idx >> 6, d = idx & 63;
            Ks[r * 65 + d] = Kg[(size_t)r * HH + d];
            Vs[r * 64 + d] = Vg[(size_t)r * HH + d];
        }
        __syncthreads();

        // S tile = Q @ K^T (4x4 per thread)
        float s[4][4] = {};
        #pragma unroll
        for (int d = 0; d < 64; d++) {
            float qv[4], kv[4];
            #pragma unroll
            for (int i = 0; i < 4; i++) qv[i] = Qs[(qr + i) * 65 + d];
            #pragma unroll
            for (int j = 0; j < 4; j++) kv[j] = Ks[(tx * 4 + j) * 65 + d];
            #pragma unroll
            for (int i = 0; i < 4; i++)
                #pragma unroll
                for (int j = 0; j < 4; j++)
                    s[i][j] += qv[i] * kv[j];
        }
        // scale + msb sigmoid gate + spec scale, write to Ps
        #pragma unroll
        for (int i = 0; i < 4; i++)
            #pragma unroll
            for (int j = 0; j < 4; j++) {
                float s0 = s[i][j] * SCALE_C;
                float e = 1.0f / (1.0f + __expf(-s0 * mh));
                Ps[(qr + i) * 65 + tx * 4 + j] = s0 * (1.0f + e * SP_C) * sp;
            }
        __syncthreads();

        // online softmax row stats (64 threads, one row each)
        if (tid < 64) {
            int r = tid;
            float* pr = &Ps[r * 65];
            float rm = mrow[r];
            #pragma unroll 8
            for (int k = 0; k < 64; k++) rm = fmaxf(rm, pr[k]);
            float c = __expf(mrow[r] - rm);
            float rs = 0.f;
            #pragma unroll 8
            for (int k = 0; k < 64; k++) {
                float p = __expf(pr[k] - rm);
                pr[k] = p;
                rs += p;
            }
            lrow[r] = lrow[r] * c + rs;
            mrow[r] = rm;
            crow[r] = c;
        }
        __syncthreads();

        // rescale accumulators, then ctx += P @ V
        #pragma unroll
        for (int i = 0; i < 4; i++) {
            float c = crow[qr + i];
            #pragma unroll
            for (int j = 0; j < 4; j++) acc[i][j] *= c;
        }
        #pragma unroll 4
        for (int k = 0; k < 64; k++) {
            float pv[4], vv[4];
            #pragma unroll
            for (int i = 0; i < 4; i++) pv[i] = Ps[(qr + i) * 65 + k];
            #pragma unroll
            for (int j = 0; j < 4; j++) vv[j] = Vs[k * 64 + vc + j];
            #pragma unroll
            for (int i = 0; i < 4; i++)
                #pragma unroll
                for (int j = 0; j < 4; j++)
                    acc[i][j] += pv[i] * vv[j];
        }
    }

    float* Cg = g_ctx + base;
    #pragma unroll
    for (int i = 0; i < 4; i++) {
        float inv = 1.0f / lrow[qr + i];
        #pragma unroll
        for (int j = 0; j < 4; j++)
            Cg[(size_t)(qr + i) * HH + vc + j] = acc[i][j] * inv;
    }
}

// ---------------- row LayerNorm ----------------
__global__ void ln_kernel(const float* __restrict__ x,
                          const float* __restrict__ g,
                          const float* __restrict__ bta,
                          float* __restrict__ out)
{
    __shared__ float r1[256];
    __shared__ float r2[256];
    int row = blockIdx.x, tid = threadIdx.x;
    const float4* xr = (const float4*)(x + (size_t)row * HH);
    float4 a = xr[tid];
    float s = a.x + a.y + a.z + a.w;
    float ss = a.x * a.x + a.y * a.y + a.z * a.z + a.w * a.w;
    r1[tid] = s; r2[tid] = ss;
    __syncthreads();
    for (int off = 128; off > 0; off >>= 1) {
        if (tid < off) { r1[tid] += r1[tid + off]; r2[tid] += r2[tid + off]; }
        __syncthreads();
    }
    float mu = r1[0] * (1.0f / HH);
    float var = r2[0] * (1.0f / HH) - mu * mu;
    float rstd = rsqrtf(var + EPS_C);
    float4 gg = ((const float4*)g)[tid];
    float4 bb = ((const float4*)bta)[tid];
    float4 o;
    o.x = (a.x - mu) * rstd * gg.x + bb.x;
    o.y = (a.y - mu) * rstd * gg.y + bb.y;
    o.z = (a.z - mu) * rstd * gg.z + bb.z;
    o.w = (a.w - mu) * rstd * gg.w + bb.w;
    ((float4*)(out + (size_t)row * HH))[tid] = o;
}

// ---------------- launch ----------------
extern "C" void kernel_launch(void* const* d_in, const int* in_sizes, int n_in,
                              void* d_out, int out_size)
{
    const float* query = (const float*)d_in[0];
    const float* key_t = (const float*)d_in[1];
    const float* value = (const float*)d_in[2];
    const float* Wq = (const float*)d_in[3];
    const float* bq = (const float*)d_in[4];
    const float* Wk = (const float*)d_in[5];
    const float* bk = (const float*)d_in[6];
    const float* Wv = (const float*)d_in[7];
    const float* bv = (const float*)d_in[8];
    const float* msb = (const float*)d_in[9];
    const float* Ws1 = (const float*)d_in[10];
    const float* bs1 = (const float*)d_in[11];
    const float* Ws2 = (const float*)d_in[12];
    const float* bs2 = (const float*)d_in[13];
    const float* Wo = (const float*)d_in[14];
    const float* bo = (const float*)d_in[15];
    const float* ln_g = (const float*)d_in[16];
    const float* ln_b = (const float*)d_in[17];

    float *pQ, *pK, *pV, *pCtx, *pPre;
    cudaGetSymbolAddress((void**)&pQ, g_Q);
    cudaGetSymbolAddress((void**)&pK, g_K);
    cudaGetSymbolAddress((void**)&pV, g_V);
    cudaGetSymbolAddress((void**)&pCtx, g_ctx);
    cudaGetSymbolAddress((void**)&pPre, g_pre);

    cudaFuncSetAttribute(attn_kernel, cudaFuncAttributeMaxDynamicSharedMemorySize,
                         ATT_SMEM_BYTES);

    dim3 gg(HH / 64, M_TOT / 64);   // (16, 32)

    // Q/K/V projections
    sgemm_kernel<<<gg, 256>>>(query, Wq, bq, nullptr, pQ, M_TOT, HH, HH);
    sgemm_kernel<<<gg, 256>>>(key_t, Wk, bk, nullptr, pK, M_TOT, HH, HH);
    sgemm_kernel<<<gg, 256>>>(value, Wv, bv, nullptr, pV, M_TOT, HH, HH);

    // per-head msb means + per-batch spec scalar
    msb_kernel<<<NHH, 256>>>(msb);
    qmean_part<<<dim3(16, BB), 256>>>(query);
    spec_kernel<<<BB, 512>>>(Ws1, bs1, Ws2, bs2);

    // fused attention (gate + spec + softmax + PV)
    attn_kernel<<<dim3(SS / 64, NHH, BB), 256, ATT_SMEM_BYTES>>>();

    // output projection + bias + residual
    sgemm_kernel<<<gg, 256>>>(pCtx, Wo, bo, query, pPre, M_TOT, HH, HH);

    // LayerNorm -> d_out
    ln_kernel<<<M_TOT, 256>>>(pPre, ln_g, ln_b, (float*)d_out);
}

// round 3
// speedup vs baseline: 1.7988x; 1.7988x over previous
#include <cuda_runtime.h>
#include <cuda_bf16.h>
#include <math.h>
#include <cstdint>

// Problem constants
#define BB 2
#define SS 1024
#define HH 1024
#define NHH 16
#define HDD 64
#define SP_C 0.05f
#define EPS_C 1e-5f
#define SCALE_C 0.125f   // 1/sqrt(64)

#define M_TOT (BB*SS)    // 2048

// ---------------- scratch (device globals: no allocations allowed) ----------
__device__ float g_Q[M_TOT*HH];
__device__ float g_K[M_TOT*HH];
__device__ float g_V[M_TOT*HH];
__device__ float g_ctx[M_TOT*HH];
__device__ float g_pre[M_TOT*HH];
__device__ float g_WT[4*HH*HH];      // transposed weights: Wq,Wk,Wv,Wo
__device__ float g_msbh[NHH];
__device__ float g_spec[BB];
__device__ float g_part[BB*16*HH];   // partial column sums of query over seq

// =====================  PTX helpers (mma.sync / cp.async)  ==================
__device__ __forceinline__ uint32_t smem_u32(const void* p) {
    uint32_t a;
    asm("{ .reg .u64 t; cvta.to.shared.u64 t, %1; cvt.u32.u64 %0, t; }"
        : "=r"(a) : "l"(p));
    return a;
}

__device__ __forceinline__ void cp16(uint32_t s, const float* g) {
    asm volatile("cp.async.cg.shared.global [%0], [%1], 16;"
                 :: "r"(s), "l"(__cvta_generic_to_global(g)));
}
#define CP_COMMIT() asm volatile("cp.async.commit_group;" ::: "memory")
#define CP_WAIT0()  asm volatile("cp.async.wait_group 0;" ::: "memory")
#define CP_WAIT1()  asm volatile("cp.async.wait_group 1;" ::: "memory")

__device__ __forceinline__ void ldsm4(uint32_t* r, uint32_t addr) {
    asm volatile("ldmatrix.sync.aligned.m8n8.x4.shared.b16 {%0,%1,%2,%3}, [%4];"
                 : "=r"(r[0]), "=r"(r[1]), "=r"(r[2]), "=r"(r[3]) : "r"(addr));
}
__device__ __forceinline__ void ldsm2(uint32_t* r, uint32_t addr) {
    asm volatile("ldmatrix.sync.aligned.m8n8.x2.shared.b16 {%0,%1}, [%2];"
                 : "=r"(r[0]), "=r"(r[1]) : "r"(addr));
}
__device__ __forceinline__ uint32_t f2tf(uint32_t x) {
    uint32_t y;
    asm("cvt.rna.tf32.f32 %0, %1;" : "=r"(y) : "r"(x));
    return y;
}
__device__ __forceinline__ void mma8(float* d, const uint32_t* a, const uint32_t* b) {
    asm volatile("mma.sync.aligned.m16n8k8.row.col.f32.tf32.tf32.f32 "
                 "{%0,%1,%2,%3}, {%4,%5,%6,%7}, {%8,%9}, {%0,%1,%2,%3};"
                 : "+f"(d[0]), "+f"(d[1]), "+f"(d[2]), "+f"(d[3])
                 : "r"(a[0]), "r"(a[1]), "r"(a[2]), "r"(a[3]),
                   "r"(b[0]), "r"(b[1]));
}

// ======================  mma.sync tf32 GEMM  ================================
// C[2048,1024] = A[2048,1024] @ W, with BT = W^T stored [N,K].
// BM=BN=128, BK=32, 256 thr (8 warps, 2x4), warp tile 64x32.
#define GK 1024
#define GN 1024
#define BKC 32
#define NKT (GK/BKC)          // 32 K-tiles
#define TSTR 36               // smem row stride in floats (144B)
#define STAGE_B (128*TSTR*4)  // 18432 B per matrix per stage
#define GSM_TOTAL (4*STAGE_B) // A0,B0,A1,B1 = 73728 B

__global__ void __launch_bounds__(256, 1)
mma_gemm(const float* __restrict__ A, const float* __restrict__ BT,
         const float* __restrict__ bias, const float* __restrict__ res,
         float* __restrict__ C)
{
    extern __shared__ char smem[];
    uint32_t sb = smem_u32(smem);
    const int tid = threadIdx.x;
    const int lane = tid & 31;
    const int wid = tid >> 5;
    const int warp_m = wid >> 2;        // 0..1
    const int warp_n = wid & 3;         // 0..3
    const int row0 = blockIdx.y * 128;
    const int col0 = blockIdx.x * 128;

    const float* Abase = A  + (size_t)row0 * GK;
    const float* Bbase = BT + (size_t)col0 * GK;

    // cp.async chunk mapping: 4 chunks per matrix per thread
    // chunk c in [0,1024): row = c>>3, seg = c&7
    auto load_stage = [&](int stage, int kt) {
        uint32_t as = sb + (stage * 2 + 0) * STAGE_B;
        uint32_t bs = sb + (stage * 2 + 1) * STAGE_B;
        const float* Ak = Abase + kt * BKC;
        const float* Bk = Bbase + kt * BKC;
        #pragma unroll
        for (int i = 0; i < 4; i++) {
            int c = tid + i * 256;
            int r = c >> 3, sg = c & 7;
            cp16(as + (uint32_t)(r * 144 + sg * 16), Ak + (size_t)r * GK + sg * 4);
            cp16(bs + (uint32_t)(r * 144 + sg * 16), Bk + (size_t)r * GK + sg * 4);
        }
        CP_COMMIT();
    };

    // ldmatrix per-thread address offsets (bytes) within a stage
    // A: row = warp_m*64 + mf*16 + (lane&15); seg = ks*2 + (lane>>4)
    // B: row = warp_n*32 + nf*8 + (lane&7);  seg = ks*2 + ((lane>>3)&1)
    uint32_t a_off[4], b_off[4];
    #pragma unroll
    for (int mf = 0; mf < 4; mf++)
        a_off[mf] = (uint32_t)((warp_m * 64 + mf * 16 + (lane & 15)) * 144
                               + (lane >> 4) * 16);
    #pragma unroll
    for (int nf = 0; nf < 4; nf++)
        b_off[nf] = (uint32_t)((warp_n * 32 + nf * 8 + (lane & 7)) * 144
                               + ((lane >> 3) & 1) * 16);

    float acc[4][4][4] = {};

    load_stage(0, 0);
    int buf = 0;
    for (int kt = 0; kt < NKT; kt++) {
        if (kt + 1 < NKT) {
            load_stage(buf ^ 1, kt + 1);
            CP_WAIT1();
        } else {
            CP_WAIT0();
        }
        __syncthreads();

        uint32_t as = sb + (buf * 2 + 0) * STAGE_B;
        uint32_t bs = sb + (buf * 2 + 1) * STAGE_B;
        #pragma unroll
        for (int ks = 0; ks < 4; ks++) {
            uint32_t a[4][4], b[4][2];
            #pragma unroll
            for (int mf = 0; mf < 4; mf++) {
                ldsm4(a[mf], as + a_off[mf] + ks * 32);
                #pragma unroll
                for (int j = 0; j < 4; j++) a[mf][j] = f2tf(a[mf][j]);
            }
            #pragma unroll
            for (int nf = 0; nf < 4; nf++) {
                ldsm2(b[nf], bs + b_off[nf] + ks * 32);
                b[nf][0] = f2tf(b[nf][0]);
                b[nf][1] = f2tf(b[nf][1]);
            }
            #pragma unroll
            for (int mf = 0; mf < 4; mf++)
                #pragma unroll
                for (int nf = 0; nf < 4; nf++)
                    mma8(acc[mf][nf], a[mf], b[nf]);
        }
        __syncthreads();
        buf ^= 1;
    }

    // epilogue: c0=(r, c), c1=(r, c+1), c2=(r+8, c), c3=(r+8, c+1)
    // r = row0 + warp_m*64 + mf*16 + lane/4 ; c = col0 + warp_n*32 + nf*8 + 2*(lane&3)
    #pragma unroll
    for (int nf = 0; nf < 4; nf++) {
        int c = col0 + warp_n * 32 + nf * 8 + 2 * (lane & 3);
        float bx = __ldg(bias + c), by = __ldg(bias + c + 1);
        #pragma unroll
        for (int mf = 0; mf < 4; mf++) {
            int r = row0 + warp_m * 64 + mf * 16 + (lane >> 2);
            float2 v0 = make_float2(acc[mf][nf][0] + bx, acc[mf][nf][1] + by);
            float2 v1 = make_float2(acc[mf][nf][2] + bx, acc[mf][nf][3] + by);
            if (res) {
                float2 r0 = *(const float2*)(res + (size_t)r * GN + c);
                float2 r1 = *(const float2*)(res + (size_t)(r + 8) * GN + c);
                v0.x += r0.x; v0.y += r0.y;
                v1.x += r1.x; v1.y += r1.y;
            }
            *(float2*)(C + (size_t)r * GN + c) = v0;
            *(float2*)(C + (size_t)(r + 8) * GN + c) = v1;
        }
    }
}

// ---------------- 1024x1024 transpose: dst[n][k] = src[k][n] ----------------
__global__ void transpose_kernel(const float* __restrict__ src, float* __restrict__ dst)
{
    __shared__ float t[32][33];
    int x = blockIdx.x * 32 + threadIdx.x;
    int y0 = blockIdx.y * 32;
    #pragma unroll
    for (int i = threadIdx.y; i < 32; i += 8)
        t[i][threadIdx.x] = src[(size_t)(y0 + i) * HH + x];
    __syncthreads();
    int xo = blockIdx.y * 32 + threadIdx.x;
    int yo0 = blockIdx.x * 32;
    #pragma unroll
    for (int i = threadIdx.y; i < 32; i += 8)
        dst[(size_t)(yo0 + i) * HH + xo] = t[threadIdx.x][i];
}

// ---------------- msb per-head mean ----------------
__global__ void msb_kernel(const float* __restrict__ msb)
{
    __shared__ float red[256];
    int h = blockIdx.x, tid = threadIdx.x;
    const float* p = msb + (size_t)h * HDD * HDD;
    float s = 0.f;
    for (int i = tid; i < HDD * HDD; i += 256) s += p[i];
    red[tid] = s;
    __syncthreads();
    for (int off = 128; off > 0; off >>= 1) {
        if (tid < off) red[tid] += red[tid + off];
        __syncthreads();
    }
    if (tid == 0) g_msbh[h] = red[0] * (1.0f / (HDD * HDD));
}

// ---------------- stage 1 of query mean over seq -------
__global__ void qmean_part(const float* __restrict__ q)
{
    int b = blockIdx.y, ch = blockIdx.x;
    int tid = threadIdx.x;
    for (int c = tid; c < HH; c += 256) {
        const float* base = q + ((size_t)b * SS + ch * 64) * HH + c;
        float s = 0.f;
        #pragma unroll 4
        for (int r = 0; r < 64; r++) s += base[(size_t)r * HH];
        g_part[((size_t)b * 16 + ch) * HH + c] = s;
    }
}

// ---------------- spec MLP: per-batch scalar -------------------------------
__global__ void spec_kernel(const float* __restrict__ Ws1, const float* __restrict__ bs1,
                            const float* __restrict__ Ws2, const float* __restrict__ bs2)
{
    __shared__ float sin_[HH];
    __shared__ float h1[HH / 2];
    __shared__ float red[512];
    int b = blockIdx.x, tid = threadIdx.x;

    for (int c = tid; c < HH; c += 512) {
        float s = 0.f;
        #pragma unroll
        for (int p = 0; p < 16; p++) s += g_part[((size_t)b * 16 + p) * HH + c];
        sin_[c] = s * (1.0f / SS);
    }
    __syncthreads();
    {
        float s = bs1[tid];
        for (int i = 0; i < HH; i++) s += sin_[i] * Ws1[(size_t)i * 512 + tid];
        h1[tid] = fmaxf(s, 0.f);
    }
    __syncthreads();
    float acc = 0.f;
    for (int c = tid; c < HH; c += 512) {
        float s = bs2[c];
        for (int i = 0; i < 512; i++) s += h1[i] * Ws2[(size_t)i * HH + c];
        acc += 1.0f / (1.0f + __expf(-s));
    }
    red[tid] = acc;
    __syncthreads();
    for (int off = 256; off > 0; off >>= 1) {
        if (tid < off) red[tid] += red[tid + off];
        __syncthreads();
    }
    if (tid == 0) g_spec[b] = red[0] * (1.0f / HH);
}

// ---------------- fused flash-style attention -------------------------------
#define ATT_SMEM_FLOATS (3*64*65 + 64*64 + 192)
#define ATT_SMEM_BYTES  (ATT_SMEM_FLOATS * 4)

__global__ void attn_kernel()
{
    extern __shared__ float sm[];
    float* Qs = sm;
    float* Ks = Qs + 64 * 65;
    float* Ps = Ks + 64 * 65;
    float* Vs = Ps + 64 * 65;
    float* mrow = Vs + 64 * 64;
    float* lrow = mrow + 64;
    float* crow = lrow + 64;

    int b = blockIdx.z, h = blockIdx.y, q0 = blockIdx.x << 6;
    int tid = threadIdx.x;
    int ty = tid >> 4, tx = tid & 15;
    int qr = ty << 2, vc = tx << 2;

    const size_t base = ((size_t)b * SS + q0) * HH + h * HDD;
    const float* Qg = g_Q + base;

    for (int idx = tid; idx < 4096; idx += 256) {
        int r = idx >> 6, d = idx & 63;
        Qs[r * 65 + d] = Qg[(size_t)r * HH + d];
    }
    if (tid < 64) { mrow[tid] = -1e30f; lrow[tid] = 0.f; }

    float acc[4][4] = {};
    float mh = g_msbh[h];
    float sp = g_spec[b];

    for (int kt = 0; kt < 16; kt++) {
        __syncthreads();
        const float* Kg = g_K + ((size_t)b * SS + kt * 64) * HH + h * HDD;
        const float* Vg = g_V + ((size_t)b * SS + kt * 64) * HH + h * HDD;
        for (int idx = tid; idx < 4096; idx += 256) {
            int r = idx >> 6, d = idx & 63;
            Ks[r * 65 + d] = Kg[(size_t)r * HH + d];
            Vs[r * 64 + d] = Vg[(size_t)r * HH + d];
        }
        __syncthreads();

        float s[4][4] = {};
        #pragma unroll
        for (int d = 0; d < 64; d++) {
            float qv[4], kv[4];
            #pragma unroll
            for (int i = 0; i < 4; i++) qv[i] = Qs[(qr + i) * 65 + d];
            #pragma unroll
            for (int j = 0; j < 4; j++) kv[j] = Ks[(tx * 4 + j) * 65 + d];
            #pragma unroll
            for (int i = 0; i < 4; i++)
                #pragma unroll
                for (int j = 0; j < 4; j++)
                    s[i][j] += qv[i] * kv[j];
        }
        #pragma unroll
        for (int i = 0; i < 4; i++)
            #pragma unroll
            for (int j = 0; j < 4; j++) {
                float s0 = s[i][j] * SCALE_C;
                float e = 1.0f / (1.0f + __expf(-s0 * mh));
                Ps[(qr + i) * 65 + tx * 4 + j] = s0 * (1.0f + e * SP_C) * sp;
            }
        __syncthreads();

        if (tid < 64) {
            int r = tid;
            float* pr = &Ps[r * 65];
            float rm = mrow[r];
            #pragma unroll 8
            for (int k = 0; k < 64; k++) rm = fmaxf(rm, pr[k]);
            float c = __expf(mrow[r] - rm);
            float rs = 0.f;
            #pragma unroll 8
            for (int k = 0; k < 64; k++) {
                float p = __expf(pr[k] - rm);
                pr[k] = p;
                rs += p;
            }
            lrow[r] = lrow[r] * c + rs;
            mrow[r] = rm;
            crow[r] = c;
        }
        __syncthreads();

        #pragma unroll
        for (int i = 0; i < 4; i++) {
            float c = crow[qr + i];
            #pragma unroll
            for (int j = 0; j < 4; j++) acc[i][j] *= c;
        }
        #pragma unroll 4
        for (int k = 0; k < 64; k++) {
            float pv[4], vv[4];
            #pragma unroll
            for (int i = 0; i < 4; i++) pv[i] = Ps[(qr + i) * 65 + k];
            #pragma unroll
            for (int j = 0; j < 4; j++) vv[j] = Vs[k * 64 + vc + j];
            #pragma unroll
            for (int i = 0; i < 4; i++)
                #pragma unroll
                for (int j = 0; j < 4; j++)
                    acc[i][j] += pv[i] * vv[j];
        }
    }

    float* Cg = g_ctx + base;
    #pragma unroll
    for (int i = 0; i < 4; i++) {
        float inv = 1.0f / lrow[qr + i];
        #pragma unroll
        for (int j = 0; j < 4; j++)
            Cg[(size_t)(qr + i) * HH + vc + j] = acc[i][j] * inv;
    }
}

// ---------------- row LayerNorm ----------------
__global__ void ln_kernel(const float* __restrict__ x,
                          const float* __restrict__ g,
                          const float* __restrict__ bta,
                          float* __restrict__ out)
{
    __shared__ float r1[256];
    __shared__ float r2[256];
    int row = blockIdx.x, tid = threadIdx.x;
    const float4* xr = (const float4*)(x + (size_t)row * HH);
    float4 a = xr[tid];
    float s = a.x + a.y + a.z + a.w;
    float ss = a.x * a.x + a.y * a.y + a.z * a.z + a.w * a.w;
    r1[tid] = s; r2[tid] = ss;
    __syncthreads();
    for (int off = 128; off > 0; off >>= 1) {
        if (tid < off) { r1[tid] += r1[tid + off]; r2[tid] += r2[tid + off]; }
        __syncthreads();
    }
    float mu = r1[0] * (1.0f / HH);
    float var = r2[0] * (1.0f / HH) - mu * mu;
    float rstd = rsqrtf(var + EPS_C);
    float4 gg = ((const float4*)g)[tid];
    float4 bb = ((const float4*)bta)[tid];
    float4 o;
    o.x = (a.x - mu) * rstd * gg.x + bb.x;
    o.y = (a.y - mu) * rstd * gg.y + bb.y;
    o.z = (a.z - mu) * rstd * gg.z + bb.z;
    o.w = (a.w - mu) * rstd * gg.w + bb.w;
    ((float4*)(out + (size_t)row * HH))[tid] = o;
}

// ---------------- launch ----------------
extern "C" void kernel_launch(void* const* d_in, const int* in_sizes, int n_in,
                              void* d_out, int out_size)
{
    const float* query = (const float*)d_in[0];
    const float* key_t = (const float*)d_in[1];
    const float* value = (const float*)d_in[2];
    const float* Wq = (const float*)d_in[3];
    const float* bq = (const float*)d_in[4];
    const float* Wk = (const float*)d_in[5];
    const float* bk = (const float*)d_in[6];
    const float* Wv = (const float*)d_in[7];
    const float* bv = (const float*)d_in[8];
    const float* msb = (const float*)d_in[9];
    const float* Ws1 = (const float*)d_in[10];
    const float* bs1 = (const float*)d_in[11];
    const float* Ws2 = (const float*)d_in[12];
    const float* bs2 = (const float*)d_in[13];
    const float* Wo = (const float*)d_in[14];
    const float* bo = (const float*)d_in[15];
    const float* ln_g = (const float*)d_in[16];
    const float* ln_b = (const float*)d_in[17];

    float *pQ, *pK, *pV, *pCtx, *pPre, *pWT;
    cudaGetSymbolAddress((void**)&pQ, g_Q);
    cudaGetSymbolAddress((void**)&pK, g_K);
    cudaGetSymbolAddress((void**)&pV, g_V);
    cudaGetSymbolAddress((void**)&pCtx, g_ctx);
    cudaGetSymbolAddress((void**)&pPre, g_pre);
    cudaGetSymbolAddress((void**)&pWT, g_WT);

    float* WTq = pWT + 0 * HH * HH;
    float* WTk = pWT + 1 * HH * HH;
    float* WTv = pWT + 2 * HH * HH;
    float* WTo = pWT + 3 * HH * HH;

    cudaFuncSetAttribute(attn_kernel, cudaFuncAttributeMaxDynamicSharedMemorySize,
                         ATT_SMEM_BYTES);
    cudaFuncSetAttribute(mma_gemm, cudaFuncAttributeMaxDynamicSharedMemorySize,
                         GSM_TOTAL);

    dim3 tb(32, 8), tg(32, 32);
    dim3 gemm_grid(GN / 128, M_TOT / 128);   // (8, 16)

    // launches 0-3: weight transposes
    transpose_kernel<<<tg, tb>>>(Wq, WTq);
    transpose_kernel<<<tg, tb>>>(Wk, WTk);
    transpose_kernel<<<tg, tb>>>(Wv, WTv);
    transpose_kernel<<<tg, tb>>>(Wo, WTo);
    // launch 4
    msb_kernel<<<NHH, 256>>>(msb);
    // launch 5 (ncu -s 5 profiles this): mma.sync tf32 GEMM
    mma_gemm<<<gemm_grid, 256, GSM_TOTAL>>>(query, WTq, bq, nullptr, pQ);
    mma_gemm<<<gemm_grid, 256, GSM_TOTAL>>>(key_t, WTk, bk, nullptr, pK);
    mma_gemm<<<gemm_grid, 256, GSM_TOTAL>>>(value, WTv, bv, nullptr, pV);

    qmean_part<<<dim3(16, BB), 256>>>(query);
    spec_kernel<<<BB, 512>>>(Ws1, bs1, Ws2, bs2);

    attn_kernel<<<dim3(SS / 64, NHH, BB), 256, ATT_SMEM_BYTES>>>();

    mma_gemm<<<gemm_grid, 256, GSM_TOTAL>>>(pCtx, WTo, bo, query, pPre);

    ln_kernel<<<M_TOT, 256>>>(pPre, ln_g, ln_b, (float*)d_out);
}

// round 4
// speedup vs baseline: 2.6408x; 1.4681x over previous
#include <cuda_runtime.h>
#include <cuda_bf16.h>
#include <math.h>
#include <cstdint>

// Problem constants
#define BB 2
#define SS 1024
#define HH 1024
#define NHH 16
#define HDD 64
#define SP_C 0.05f
#define EPS_C 1e-5f
#define SCALE_C 0.125f   // 1/sqrt(64)

#define M_TOT (BB*SS)    // 2048

// ---------------- scratch (device globals: no allocations allowed) ----------
__device__ float g_Q[M_TOT*HH];
__device__ float g_K[M_TOT*HH];
__device__ float g_V[M_TOT*HH];
__device__ float g_VT[BB*NHH*HDD*SS];   // V transposed per (b,h): [d][s]
__device__ float g_ctx[M_TOT*HH];
__device__ float g_pre[M_TOT*HH];
__device__ float g_WT[4*HH*HH];      // transposed weights: Wq,Wk,Wv,Wo
__device__ float g_msbh[NHH];
__device__ float g_spec[BB];
__device__ float g_part[BB*16*HH];   // partial column sums of query over seq

// =====================  PTX helpers (mma.sync / cp.async)  ==================
__device__ __forceinline__ uint32_t smem_u32(const void* p) {
    uint32_t a;
    asm("{ .reg .u64 t; cvta.to.shared.u64 t, %1; cvt.u32.u64 %0, t; }"
        : "=r"(a) : "l"(p));
    return a;
}

__device__ __forceinline__ void cp16(uint32_t s, const float* g) {
    asm volatile("cp.async.cg.shared.global [%0], [%1], 16;"
                 :: "r"(s), "l"(__cvta_generic_to_global(g)));
}
#define CP_COMMIT() asm volatile("cp.async.commit_group;" ::: "memory")
#define CP_WAIT0()  asm volatile("cp.async.wait_group 0;" ::: "memory")
#define CP_WAIT1()  asm volatile("cp.async.wait_group 1;" ::: "memory")

__device__ __forceinline__ void ldsm4(uint32_t* r, uint32_t addr) {
    asm volatile("ldmatrix.sync.aligned.m8n8.x4.shared.b16 {%0,%1,%2,%3}, [%4];"
                 : "=r"(r[0]), "=r"(r[1]), "=r"(r[2]), "=r"(r[3]) : "r"(addr));
}
__device__ __forceinline__ void ldsm2(uint32_t* r, uint32_t addr) {
    asm volatile("ldmatrix.sync.aligned.m8n8.x2.shared.b16 {%0,%1}, [%2];"
                 : "=r"(r[0]), "=r"(r[1]) : "r"(addr));
}
__device__ __forceinline__ uint32_t f2tf(uint32_t x) {
    uint32_t y;
    asm("cvt.rna.tf32.f32 %0, %1;" : "=r"(y) : "r"(x));
    return y;
}
__device__ __forceinline__ float f2tf_f(float x) {
    uint32_t y;
    asm("cvt.rna.tf32.f32 %0, %1;" : "=r"(y) : "f"(x));
    return __uint_as_float(y);
}
__device__ __forceinline__ void mma8(float* d, const uint32_t* a, const uint32_t* b) {
    asm volatile("mma.sync.aligned.m16n8k8.row.col.f32.tf32.tf32.f32 "
                 "{%0,%1,%2,%3}, {%4,%5,%6,%7}, {%8,%9}, {%0,%1,%2,%3};"
                 : "+f"(d[0]), "+f"(d[1]), "+f"(d[2]), "+f"(d[3])
                 : "r"(a[0]), "r"(a[1]), "r"(a[2]), "r"(a[3]),
                   "r"(b[0]), "r"(b[1]));
}

// ======================  mma.sync tf32 GEMM  ================================
// C[2048,1024] = A[2048,1024] @ W, with BT = W^T stored [N,K].
// BM=BN=128, BK=32, 256 thr (8 warps, 2x4), warp tile 64x32.
#define GK 1024
#define GN 1024
#define BKC 32
#define NKT (GK/BKC)          // 32 K-tiles
#define TSTR 36               // smem row stride in floats (144B)
#define STAGE_B (128*TSTR*4)  // 18432 B per matrix per stage
#define GSM_TOTAL (4*STAGE_B) // A0,B0,A1,B1 = 73728 B

__global__ void __launch_bounds__(256, 1)
mma_gemm(const float* __restrict__ A, const float* __restrict__ BT,
         const float* __restrict__ bias, const float* __restrict__ res,
         float* __restrict__ C)
{
    extern __shared__ char smem[];
    uint32_t sb = smem_u32(smem);
    const int tid = threadIdx.x;
    const int lane = tid & 31;
    const int wid = tid >> 5;
    const int warp_m = wid >> 2;        // 0..1
    const int warp_n = wid & 3;         // 0..3
    const int row0 = blockIdx.y * 128;
    const int col0 = blockIdx.x * 128;

    const float* Abase = A  + (size_t)row0 * GK;
    const float* Bbase = BT + (size_t)col0 * GK;

    auto load_stage = [&](int stage, int kt) {
        uint32_t as = sb + (stage * 2 + 0) * STAGE_B;
        uint32_t bs = sb + (stage * 2 + 1) * STAGE_B;
        const float* Ak = Abase + kt * BKC;
        const float* Bk = Bbase + kt * BKC;
        #pragma unroll
        for (int i = 0; i < 4; i++) {
            int c = tid + i * 256;
            int r = c >> 3, sg = c & 7;
            cp16(as + (uint32_t)(r * 144 + sg * 16), Ak + (size_t)r * GK + sg * 4);
            cp16(bs + (uint32_t)(r * 144 + sg * 16), Bk + (size_t)r * GK + sg * 4);
        }
        CP_COMMIT();
    };

    uint32_t a_off[4], b_off[4];
    #pragma unroll
    for (int mf = 0; mf < 4; mf++)
        a_off[mf] = (uint32_t)((warp_m * 64 + mf * 16 + (lane & 15)) * 144
                               + (lane >> 4) * 16);
    #pragma unroll
    for (int nf = 0; nf < 4; nf++)
        b_off[nf] = (uint32_t)((warp_n * 32 + nf * 8 + (lane & 7)) * 144
                               + ((lane >> 3) & 1) * 16);

    float acc[4][4][4] = {};

    load_stage(0, 0);
    int buf = 0;
    for (int kt = 0; kt < NKT; kt++) {
        if (kt + 1 < NKT) {
            load_stage(buf ^ 1, kt + 1);
            CP_WAIT1();
        } else {
            CP_WAIT0();
        }
        __syncthreads();

        uint32_t as = sb + (buf * 2 + 0) * STAGE_B;
        uint32_t bs = sb + (buf * 2 + 1) * STAGE_B;
        #pragma unroll
        for (int ks = 0; ks < 4; ks++) {
            uint32_t a[4][4], b[4][2];
            #pragma unroll
            for (int mf = 0; mf < 4; mf++) {
                ldsm4(a[mf], as + a_off[mf] + ks * 32);
                #pragma unroll
                for (int j = 0; j < 4; j++) a[mf][j] = f2tf(a[mf][j]);
            }
            #pragma unroll
            for (int nf = 0; nf < 4; nf++) {
                ldsm2(b[nf], bs + b_off[nf] + ks * 32);
                b[nf][0] = f2tf(b[nf][0]);
                b[nf][1] = f2tf(b[nf][1]);
            }
            #pragma unroll
            for (int mf = 0; mf < 4; mf++)
                #pragma unroll
                for (int nf = 0; nf < 4; nf++)
                    mma8(acc[mf][nf], a[mf], b[nf]);
        }
        __syncthreads();
        buf ^= 1;
    }

    #pragma unroll
    for (int nf = 0; nf < 4; nf++) {
        int c = col0 + warp_n * 32 + nf * 8 + 2 * (lane & 3);
        float bx = __ldg(bias + c), by = __ldg(bias + c + 1);
        #pragma unroll
        for (int mf = 0; mf < 4; mf++) {
            int r = row0 + warp_m * 64 + mf * 16 + (lane >> 2);
            float2 v0 = make_float2(acc[mf][nf][0] + bx, acc[mf][nf][1] + by);
            float2 v1 = make_float2(acc[mf][nf][2] + bx, acc[mf][nf][3] + by);
            if (res) {
                float2 r0 = *(const float2*)(res + (size_t)r * GN + c);
                float2 r1 = *(const float2*)(res + (size_t)(r + 8) * GN + c);
                v0.x += r0.x; v0.y += r0.y;
                v1.x += r1.x; v1.y += r1.y;
            }
            *(float2*)(C + (size_t)r * GN + c) = v0;
            *(float2*)(C + (size_t)(r + 8) * GN + c) = v1;
        }
    }
}

// ---------------- 1024x1024 transpose: dst[n][k] = src[k][n] ----------------
__global__ void transpose_kernel(const float* __restrict__ src, float* __restrict__ dst)
{
    __shared__ float t[32][33];
    int x = blockIdx.x * 32 + threadIdx.x;
    int y0 = blockIdx.y * 32;
    #pragma unroll
    for (int i = threadIdx.y; i < 32; i += 8)
        t[i][threadIdx.x] = src[(size_t)(y0 + i) * HH + x];
    __syncthreads();
    int xo = blockIdx.y * 32 + threadIdx.x;
    int yo0 = blockIdx.x * 32;
    #pragma unroll
    for (int i = threadIdx.y; i < 32; i += 8)
        dst[(size_t)(yo0 + i) * HH + xo] = t[threadIdx.x][i];
}

// ---------------- per-(b,h) V transpose: VT[b][h][d][s] = V[b][s][h*64+d] ---
__global__ void vtrans_kernel(const float* __restrict__ V, float* __restrict__ VT)
{
    __shared__ float t[32][33];
    int bh = blockIdx.z;                 // b*16 + h
    int s0 = blockIdx.x * 32, d0 = blockIdx.y * 32;
    int b = bh >> 4, h = bh & 15;
    const float* src = V + ((size_t)b * SS + s0) * HH + h * HDD + d0;
    #pragma unroll
    for (int i = threadIdx.y; i < 32; i += 8)
        t[i][threadIdx.x] = src[(size_t)i * HH + threadIdx.x];
    __syncthreads();
    float* dst = VT + ((size_t)bh * HDD + d0) * SS + s0;
    #pragma unroll
    for (int i = threadIdx.y; i < 32; i += 8)
        dst[(size_t)i * SS + threadIdx.x] = t[threadIdx.x][i];
}

// ---------------- msb per-head mean ----------------
__global__ void msb_kernel(const float* __restrict__ msb)
{
    __shared__ float red[256];
    int h = blockIdx.x, tid = threadIdx.x;
    const float* p = msb + (size_t)h * HDD * HDD;
    float s = 0.f;
    for (int i = tid; i < HDD * HDD; i += 256) s += p[i];
    red[tid] = s;
    __syncthreads();
    for (int off = 128; off > 0; off >>= 1) {
        if (tid < off) red[tid] += red[tid + off];
        __syncthreads();
    }
    if (tid == 0) g_msbh[h] = red[0] * (1.0f / (HDD * HDD));
}

// ---------------- stage 1 of query mean over seq -------
__global__ void qmean_part(const float* __restrict__ q)
{
    int b = blockIdx.y, ch = blockIdx.x;
    int tid = threadIdx.x;
    for (int c = tid; c < HH; c += 256) {
        const float* base = q + ((size_t)b * SS + ch * 64) * HH + c;
        float s = 0.f;
        #pragma unroll 4
        for (int r = 0; r < 64; r++) s += base[(size_t)r * HH];
        g_part[((size_t)b * 16 + ch) * HH + c] = s;
    }
}

// ---------------- spec MLP: per-batch scalar -------------------------------
__global__ void spec_kernel(const float* __restrict__ Ws1, const float* __restrict__ bs1,
                            const float* __restrict__ Ws2, const float* __restrict__ bs2)
{
    __shared__ float sin_[HH];
    __shared__ float h1[HH / 2];
    __shared__ float red[512];
    int b = blockIdx.x, tid = threadIdx.x;

    for (int c = tid; c < HH; c += 512) {
        float s = 0.f;
        #pragma unroll
        for (int p = 0; p < 16; p++) s += g_part[((size_t)b * 16 + p) * HH + c];
        sin_[c] = s * (1.0f / SS);
    }
    __syncthreads();
    {
        float s = bs1[tid];
        for (int i = 0; i < HH; i++) s += sin_[i] * Ws1[(size_t)i * 512 + tid];
        h1[tid] = fmaxf(s, 0.f);
    }
    __syncthreads();
    float acc = 0.f;
    for (int c = tid; c < HH; c += 512) {
        float s = bs2[c];
        for (int i = 0; i < 512; i++) s += h1[i] * Ws2[(size_t)i * HH + c];
        acc += 1.0f / (1.0f + __expf(-s));
    }
    red[tid] = acc;
    __syncthreads();
    for (int off = 256; off > 0; off >>= 1) {
        if (tid < off) red[tid] += red[tid + off];
        __syncthreads();
    }
    if (tid == 0) g_spec[b] = red[0] * (1.0f / HH);
}

// ================  tensor-core flash attention  =============================
// CTA: 128 q-rows of one (b,h). 8 warps, 16 q-rows each (full 64-key width).
// smem tiles, row stride 68 floats (272B): conflict-free ldmatrix.
#define ASTR 272                       // bytes per smem row
#define AQ_OFF 0                       // Q: 128 rows
#define AK_OFF (AQ_OFF + 128*ASTR)     // K: 64 rows
#define AV_OFF (AK_OFF + 64*ASTR)      // VT: 64 rows (d-major)
#define AP_OFF (AV_OFF + 64*ASTR)      // P: 128 rows
#define A_SMEM (AP_OFF + 128*ASTR)     // 104448 bytes

__global__ void __launch_bounds__(256, 2)
attn_mma()
{
    extern __shared__ char smem[];
    uint32_t sb = smem_u32(smem);
    const int tid = threadIdx.x;
    const int lane = tid & 31;
    const int w = tid >> 5;
    const int b = blockIdx.z, h = blockIdx.y, q0 = blockIdx.x << 7;

    // ldmatrix base addresses
    const uint32_t Qa = sb + AQ_OFF + (uint32_t)((16 * w + (lane & 15)) * ASTR + (lane >> 4) * 16);
    const uint32_t Pa = sb + AP_OFF + (uint32_t)((16 * w + (lane & 15)) * ASTR + (lane >> 4) * 16);
    const uint32_t Kb = sb + AK_OFF + (uint32_t)(((((lane >> 4) << 3) + (lane & 7)) * ASTR) + ((lane >> 3) & 1) * 16);
    const uint32_t Vb = sb + AV_OFF + (uint32_t)(((((lane >> 4) << 3) + (lane & 7)) * ASTR) + ((lane >> 3) & 1) * 16);

    // load Q tile (128 x 64)
    {
        const float* Qg = g_Q + ((size_t)b * SS + q0) * HH + h * HDD;
        #pragma unroll
        for (int i = 0; i < 8; i++) {
            int f = tid + i * 256;
            int r = f >> 4, c4 = f & 15;
            cp16(sb + AQ_OFF + (uint32_t)(r * ASTR + c4 * 16),
                 Qg + (size_t)r * HH + c4 * 4);
        }
        CP_COMMIT();
    }

    const float mh = g_msbh[h];
    const float sp = g_spec[b];

    float oacc[8][4] = {};
    float m0 = -1e30f, m1 = -1e30f, l0 = 0.f, l1 = 0.f;

    for (int kt = 0; kt < 16; kt++) {
        __syncthreads();   // previous iteration done reading K/VT
        {
            const float* Kg = g_K + ((size_t)b * SS + kt * 64) * HH + h * HDD;
            const float* Vg = g_VT + (size_t)(b * NHH + h) * HDD * SS + kt * 64;
            #pragma unroll
            for (int i = 0; i < 4; i++) {
                int f = tid + i * 256;
                int r = f >> 4, c4 = f & 15;
                cp16(sb + AK_OFF + (uint32_t)(r * ASTR + c4 * 16),
                     Kg + (size_t)r * HH + c4 * 4);
                cp16(sb + AV_OFF + (uint32_t)(r * ASTR + c4 * 16),
                     Vg + (size_t)r * SS + c4 * 4);
            }
            CP_COMMIT();
        }
        CP_WAIT0();
        __syncthreads();

        // ---- S = Q @ K^T  (16 q-rows x 64 keys per warp) ----
        float sacc[8][4] = {};
        #pragma unroll
        for (int ks = 0; ks < 8; ks++) {
            uint32_t a[4];
            ldsm4(a, Qa + ks * 32);
            #pragma unroll
            for (int j = 0; j < 4; j++) a[j] = f2tf(a[j]);
            #pragma unroll
            for (int kb = 0; kb < 4; kb++) {
                uint32_t bb[4];
                ldsm4(bb, Kb + kb * 16 * ASTR + ks * 32);
                #pragma unroll
                for (int j = 0; j < 4; j++) bb[j] = f2tf(bb[j]);
                mma8(sacc[2 * kb],     a, bb);
                mma8(sacc[2 * kb + 1], a, bb + 2);
            }
        }

        // ---- gate + online softmax (rows r0 = 16w + lane/4, r1 = r0+8) ----
        float tm0 = -1e30f, tm1 = -1e30f;
        #pragma unroll
        for (int nf = 0; nf < 8; nf++) {
            #pragma unroll
            for (int j = 0; j < 4; j++) {
                float s0 = sacc[nf][j] * SCALE_C;
                float e = 1.0f / (1.0f + __expf(-s0 * mh));
                float p = s0 * (1.0f + e * SP_C) * sp;
                sacc[nf][j] = p;
                if (j < 2) tm0 = fmaxf(tm0, p); else tm1 = fmaxf(tm1, p);
            }
        }
        tm0 = fmaxf(tm0, __shfl_xor_sync(0xffffffff, tm0, 1));
        tm0 = fmaxf(tm0, __shfl_xor_sync(0xffffffff, tm0, 2));
        tm1 = fmaxf(tm1, __shfl_xor_sync(0xffffffff, tm1, 1));
        tm1 = fmaxf(tm1, __shfl_xor_sync(0xffffffff, tm1, 2));

        float nm0 = fmaxf(m0, tm0), nm1 = fmaxf(m1, tm1);
        float sc0 = __expf(m0 - nm0), sc1 = __expf(m1 - nm1);
        float su0 = 0.f, su1 = 0.f;
        #pragma unroll
        for (int nf = 0; nf < 8; nf++) {
            float p0 = __expf(sacc[nf][0] - nm0);
            float p1 = __expf(sacc[nf][1] - nm0);
            float p2 = __expf(sacc[nf][2] - nm1);
            float p3 = __expf(sacc[nf][3] - nm1);
            su0 += p0 + p1; su1 += p2 + p3;
            sacc[nf][0] = p0; sacc[nf][1] = p1;
            sacc[nf][2] = p2; sacc[nf][3] = p3;
        }
        su0 += __shfl_xor_sync(0xffffffff, su0, 1);
        su0 += __shfl_xor_sync(0xffffffff, su0, 2);
        su1 += __shfl_xor_sync(0xffffffff, su1, 1);
        su1 += __shfl_xor_sync(0xffffffff, su1, 2);
        l0 = l0 * sc0 + su0;
        l1 = l1 * sc1 + su1;
        m0 = nm0; m1 = nm1;

        #pragma unroll
        for (int nf = 0; nf < 8; nf++) {
            oacc[nf][0] *= sc0; oacc[nf][1] *= sc0;
            oacc[nf][2] *= sc1; oacc[nf][3] *= sc1;
        }

        // ---- write P (tf32-rounded) to smem ----
        {
            int r0 = 16 * w + (lane >> 2);
            uint32_t p0a = sb + AP_OFF + (uint32_t)(r0 * ASTR + 2 * (lane & 3) * 4);
            #pragma unroll
            for (int nf = 0; nf < 8; nf++) {
                float2 v0 = make_float2(f2tf_f(sacc[nf][0]), f2tf_f(sacc[nf][1]));
                float2 v1 = make_float2(f2tf_f(sacc[nf][2]), f2tf_f(sacc[nf][3]));
                *(float2*)(smem + (p0a - sb) + nf * 32) = v0;
                *(float2*)(smem + (p0a - sb) + 8 * ASTR + nf * 32) = v1;
            }
        }
        __syncwarp();

        // ---- O += P @ V ----
        #pragma unroll
        for (int ks = 0; ks < 8; ks++) {
            uint32_t a[4];
            ldsm4(a, Pa + ks * 32);
            #pragma unroll
            for (int db = 0; db < 4; db++) {
                uint32_t bb[4];
                ldsm4(bb, Vb + db * 16 * ASTR + ks * 32);
                #pragma unroll
                for (int j = 0; j < 4; j++) bb[j] = f2tf(bb[j]);
                mma8(oacc[2 * db],     a, bb);
                mma8(oacc[2 * db + 1], a, bb + 2);
            }
        }
    }

    // ---- epilogue: normalize + store ctx ----
    float inv0 = 1.0f / l0, inv1 = 1.0f / l1;
    float* Og = g_ctx + ((size_t)b * SS + q0) * HH + h * HDD;
    int r0 = 16 * w + (lane >> 2);
    #pragma unroll
    for (int nf = 0; nf < 8; nf++) {
        int c = 8 * nf + 2 * (lane & 3);
        *(float2*)&Og[(size_t)r0 * HH + c] =
            make_float2(oacc[nf][0] * inv0, oacc[nf][1] * inv0);
        *(float2*)&Og[(size_t)(r0 + 8) * HH + c] =
            make_float2(oacc[nf][2] * inv1, oacc[nf][3] * inv1);
    }
}

// ---------------- row LayerNorm ----------------
__global__ void ln_kernel(const float* __restrict__ x,
                          const float* __restrict__ g,
                          const float* __restrict__ bta,
                          float* __restrict__ out)
{
    __shared__ float r1[256];
    __shared__ float r2[256];
    int row = blockIdx.x, tid = threadIdx.x;
    const float4* xr = (const float4*)(x + (size_t)row * HH);
    float4 a = xr[tid];
    float s = a.x + a.y + a.z + a.w;
    float ss = a.x * a.x + a.y * a.y + a.z * a.z + a.w * a.w;
    r1[tid] = s; r2[tid] = ss;
    __syncthreads();
    for (int off = 128; off > 0; off >>= 1) {
        if (tid < off) { r1[tid] += r1[tid + off]; r2[tid] += r2[tid + off]; }
        __syncthreads();
    }
    float mu = r1[0] * (1.0f / HH);
    float var = r2[0] * (1.0f / HH) - mu * mu;
    float rstd = rsqrtf(var + EPS_C);
    float4 gg = ((const float4*)g)[tid];
    float4 bb = ((const float4*)bta)[tid];
    float4 o;
    o.x = (a.x - mu) * rstd * gg.x + bb.x;
    o.y = (a.y - mu) * rstd * gg.y + bb.y;
    o.z = (a.z - mu) * rstd * gg.z + bb.z;
    o.w = (a.w - mu) * rstd * gg.w + bb.w;
    ((float4*)(out + (size_t)row * HH))[tid] = o;
}

// ---------------- launch ----------------
extern "C" void kernel_launch(void* const* d_in, const int* in_sizes, int n_in,
                              void* d_out, int out_size)
{
    const float* query = (const float*)d_in[0];
    const float* key_t = (const float*)d_in[1];
    const float* value = (const float*)d_in[2];
    const float* Wq = (const float*)d_in[3];
    const float* bq = (const float*)d_in[4];
    const float* Wk = (const float*)d_in[5];
    const float* bk = (const float*)d_in[6];
    const float* Wv = (const float*)d_in[7];
    const float* bv = (const float*)d_in[8];
    const float* msb = (const float*)d_in[9];
    const float* Ws1 = (const float*)d_in[10];
    const float* bs1 = (const float*)d_in[11];
    const float* Ws2 = (const float*)d_in[12];
    const float* bs2 = (const float*)d_in[13];
    const float* Wo = (const float*)d_in[14];
    const float* bo = (const float*)d_in[15];
    const float* ln_g = (const float*)d_in[16];
    const float* ln_b = (const float*)d_in[17];

    float *pQ, *pK, *pV, *pVT, *pCtx, *pPre, *pWT;
    cudaGetSymbolAddress((void**)&pQ, g_Q);
    cudaGetSymbolAddress((void**)&pK, g_K);
    cudaGetSymbolAddress((void**)&pV, g_V);
    cudaGetSymbolAddress((void**)&pVT, g_VT);
    cudaGetSymbolAddress((void**)&pCtx, g_ctx);
    cudaGetSymbolAddress((void**)&pPre, g_pre);
    cudaGetSymbolAddress((void**)&pWT, g_WT);

    float* WTq = pWT + 0 * HH * HH;
    float* WTk = pWT + 1 * HH * HH;
    float* WTv = pWT + 2 * HH * HH;
    float* WTo = pWT + 3 * HH * HH;

    cudaFuncSetAttribute(mma_gemm, cudaFuncAttributeMaxDynamicSharedMemorySize,
                         GSM_TOTAL);
    cudaFuncSetAttribute(attn_mma, cudaFuncAttributeMaxDynamicSharedMemorySize,
                         A_SMEM);

    dim3 tb(32, 8), tg(32, 32);
    dim3 gemm_grid(GN / 128, M_TOT / 128);   // (8, 16)

    // launches 0-3: weight transposes
    transpose_kernel<<<tg, tb>>>(Wq, WTq);
    transpose_kernel<<<tg, tb>>>(Wk, WTk);
    transpose_kernel<<<tg, tb>>>(Wv, WTv);
    transpose_kernel<<<tg, tb>>>(Wo, WTo);
    // launch 4
    msb_kernel<<<NHH, 256>>>(msb);
    // launch 5 (ncu -s 5 profiles this): mma.sync tf32 GEMM
    mma_gemm<<<gemm_grid, 256, GSM_TOTAL>>>(query, WTq, bq, nullptr, pQ);
    mma_gemm<<<gemm_grid, 256, GSM_TOTAL>>>(key_t, WTk, bk, nullptr, pK);
    mma_gemm<<<gemm_grid, 256, GSM_TOTAL>>>(value, WTv, bv, nullptr, pV);

    // per-(b,h) V transpose for attention B-operand
    vtrans_kernel<<<dim3(SS / 32, HDD / 32, BB * NHH), tb>>>(pV, pVT);

    qmean_part<<<dim3(16, BB), 256>>>(query);
    spec_kernel<<<BB, 512>>>(Ws1, bs1, Ws2, bs2);

    // tensor-core flash attention
    attn_mma<<<dim3(SS / 128, NHH, BB), 256, A_SMEM>>>();

    mma_gemm<<<gemm_grid, 256, GSM_TOTAL>>>(pCtx, WTo, bo, query, pPre);

    ln_kernel<<<M_TOT, 256>>>(pPre, ln_g, ln_b, (float*)d_out);
}

// round 5
// speedup vs baseline: 3.0902x; 1.1702x over previous
#include <cuda_runtime.h>
#include <cuda_bf16.h>
#include <math.h>
#include <cstdint>

// Problem constants
#define BB 2
#define SS 1024
#define HH 1024
#define NHH 16
#define HDD 64
#define SP_C 0.05f
#define EPS_C 1e-5f
#define SCALE_C 0.125f   // 1/sqrt(64)

#define M_TOT (BB*SS)    // 2048

// ---------------- scratch (device globals: no allocations allowed) ----------
__device__ float g_Q[M_TOT*HH];
__device__ float g_K[M_TOT*HH];
__device__ float g_V[M_TOT*HH];
__device__ float g_VT[BB*NHH*HDD*SS];   // V transposed per (b,h): [d][s]
__device__ float g_ctx[M_TOT*HH];
__device__ float g_pre[M_TOT*HH];
__device__ float g_WT[4*HH*HH];      // transposed tf32-rounded weights
__device__ float g_spec[BB];
__device__ float g_part[BB*16*HH];   // partial column sums of query over seq
__device__ float g_h1p[BB*8*512];    // spec layer-1 partials

// =====================  PTX helpers (mma.sync / cp.async)  ==================
__device__ __forceinline__ uint32_t smem_u32(const void* p) {
    uint32_t a;
    asm("{ .reg .u64 t; cvta.to.shared.u64 t, %1; cvt.u32.u64 %0, t; }"
        : "=r"(a) : "l"(p));
    return a;
}

__device__ __forceinline__ void cp16(uint32_t s, const float* g) {
    asm volatile("cp.async.cg.shared.global [%0], [%1], 16;"
                 :: "r"(s), "l"(__cvta_generic_to_global(g)));
}
#define CP_COMMIT() asm volatile("cp.async.commit_group;" ::: "memory")
#define CP_WAIT0()  asm volatile("cp.async.wait_group 0;" ::: "memory")
#define CP_WAIT1()  asm volatile("cp.async.wait_group 1;" ::: "memory")

__device__ __forceinline__ void ldsm4(uint32_t* r, uint32_t addr) {
    asm volatile("ldmatrix.sync.aligned.m8n8.x4.shared.b16 {%0,%1,%2,%3}, [%4];"
                 : "=r"(r[0]), "=r"(r[1]), "=r"(r[2]), "=r"(r[3]) : "r"(addr));
}
__device__ __forceinline__ void ldsm2(uint32_t* r, uint32_t addr) {
    asm volatile("ldmatrix.sync.aligned.m8n8.x2.shared.b16 {%0,%1}, [%2];"
                 : "=r"(r[0]), "=r"(r[1]) : "r"(addr));
}
__device__ __forceinline__ uint32_t f2tf(uint32_t x) {
    uint32_t y;
    asm("cvt.rna.tf32.f32 %0, %1;" : "=r"(y) : "r"(x));
    return y;
}
__device__ __forceinline__ float f2tf_f(float x) {
    uint32_t y;
    asm("cvt.rna.tf32.f32 %0, %1;" : "=r"(y) : "f"(x));
    return __uint_as_float(y);
}
__device__ __forceinline__ void mma8(float* d, const uint32_t* a, const uint32_t* b) {
    asm volatile("mma.sync.aligned.m16n8k8.row.col.f32.tf32.tf32.f32 "
                 "{%0,%1,%2,%3}, {%4,%5,%6,%7}, {%8,%9}, {%0,%1,%2,%3};"
                 : "+f"(d[0]), "+f"(d[1]), "+f"(d[2]), "+f"(d[3])
                 : "r"(a[0]), "r"(a[1]), "r"(a[2]), "r"(a[3]),
                   "r"(b[0]), "r"(b[1]));
}

// ======================  mma.sync tf32 GEMM body  ===========================
// C[2048,1024] = A[2048,1024] @ W, with BT = W^T stored [N,K], tf32-rounded.
// BM=BN=128, BK=32, 256 thr (8 warps, 2x4), warp tile 64x32.
#define GK 1024
#define GN 1024
#define BKC 32
#define NKT (GK/BKC)          // 32 K-tiles
#define STAGE_B (128*36*4)    // 18432 B per matrix per stage
#define GSM_TOTAL (4*STAGE_B) // A0,B0,A1,B1 = 73728 B

template<bool CVTA, bool ROUND_OUT>
__device__ __forceinline__ void gemm_body(
    char* smem, const float* __restrict__ A, const float* __restrict__ BT,
    const float* __restrict__ bias, const float* __restrict__ res,
    float* __restrict__ C, int bx, int by)
{
    uint32_t sb = smem_u32(smem);
    const int tid = threadIdx.x;
    const int lane = tid & 31;
    const int wid = tid >> 5;
    const int warp_m = wid >> 2;        // 0..1
    const int warp_n = wid & 3;         // 0..3
    const int row0 = by * 128;
    const int col0 = bx * 128;

    const float* Abase = A  + (size_t)row0 * GK;
    const float* Bbase = BT + (size_t)col0 * GK;

    auto load_stage = [&](int stage, int kt) {
        uint32_t as = sb + (stage * 2 + 0) * STAGE_B;
        uint32_t bs = sb + (stage * 2 + 1) * STAGE_B;
        const float* Ak = Abase + kt * BKC;
        const float* Bk = Bbase + kt * BKC;
        #pragma unroll
        for (int i = 0; i < 4; i++) {
            int c = tid + i * 256;
            int r = c >> 3, sg = c & 7;
            cp16(as + (uint32_t)(r * 144 + sg * 16), Ak + (size_t)r * GK + sg * 4);
            cp16(bs + (uint32_t)(r * 144 + sg * 16), Bk + (size_t)r * GK + sg * 4);
        }
        CP_COMMIT();
    };

    uint32_t a_off[4], b_off[4];
    #pragma unroll
    for (int mf = 0; mf < 4; mf++)
        a_off[mf] = (uint32_t)((warp_m * 64 + mf * 16 + (lane & 15)) * 144
                               + (lane >> 4) * 16);
    #pragma unroll
    for (int nf = 0; nf < 4; nf++)
        b_off[nf] = (uint32_t)((warp_n * 32 + nf * 8 + (lane & 7)) * 144
                               + ((lane >> 3) & 1) * 16);

    float acc[4][4][4] = {};

    load_stage(0, 0);
    int buf = 0;
    for (int kt = 0; kt < NKT; kt++) {
        if (kt + 1 < NKT) {
            load_stage(buf ^ 1, kt + 1);
            CP_WAIT1();
        } else {
            CP_WAIT0();
        }
        __syncthreads();

        uint32_t as = sb + (buf * 2 + 0) * STAGE_B;
        uint32_t bs = sb + (buf * 2 + 1) * STAGE_B;
        #pragma unroll
        for (int ks = 0; ks < 4; ks++) {
            uint32_t a[4][4], b[4][2];
            #pragma unroll
            for (int mf = 0; mf < 4; mf++) {
                ldsm4(a[mf], as + a_off[mf] + ks * 32);
                if (CVTA) {
                    #pragma unroll
                    for (int j = 0; j < 4; j++) a[mf][j] = f2tf(a[mf][j]);
                }
            }
            #pragma unroll
            for (int nf = 0; nf < 4; nf++)
                ldsm2(b[nf], bs + b_off[nf] + ks * 32);
            #pragma unroll
            for (int mf = 0; mf < 4; mf++)
                #pragma unroll
                for (int nf = 0; nf < 4; nf++)
                    mma8(acc[mf][nf], a[mf], b[nf]);
        }
        __syncthreads();
        buf ^= 1;
    }

    #pragma unroll
    for (int nf = 0; nf < 4; nf++) {
        int c = col0 + warp_n * 32 + nf * 8 + 2 * (lane & 3);
        float bx_ = __ldg(bias + c), by_ = __ldg(bias + c + 1);
        #pragma unroll
        for (int mf = 0; mf < 4; mf++) {
            int r = row0 + warp_m * 64 + mf * 16 + (lane >> 2);
            float2 v0 = make_float2(acc[mf][nf][0] + bx_, acc[mf][nf][1] + by_);
            float2 v1 = make_float2(acc[mf][nf][2] + bx_, acc[mf][nf][3] + by_);
            if (res) {
                float2 r0 = *(const float2*)(res + (size_t)r * GN + c);
                float2 r1 = *(const float2*)(res + (size_t)(r + 8) * GN + c);
                v0.x += r0.x; v0.y += r0.y;
                v1.x += r1.x; v1.y += r1.y;
            }
            if (ROUND_OUT) {
                v0.x = f2tf_f(v0.x); v0.y = f2tf_f(v0.y);
                v1.x = f2tf_f(v1.x); v1.y = f2tf_f(v1.y);
            }
            *(float2*)(C + (size_t)r * GN + c) = v0;
            *(float2*)(C + (size_t)(r + 8) * GN + c) = v1;
        }
    }
}

// fused Q/K/V projection: grid.z picks which
__global__ void __launch_bounds__(256, 1)
qkv_gemm(const float* q, const float* k, const float* v,
         const float* wq, const float* wk, const float* wv,
         const float* bq, const float* bk, const float* bv,
         float* oq, float* ok, float* ov)
{
    extern __shared__ char smem[];
    int z = blockIdx.z;
    const float* A  = (z == 0) ? q  : (z == 1) ? k  : v;
    const float* BT = (z == 0) ? wq : (z == 1) ? wk : wv;
    const float* bi = (z == 0) ? bq : (z == 1) ? bk : bv;
    float* C        = (z == 0) ? oq : (z == 1) ? ok : ov;
    gemm_body<true, true>(smem, A, BT, bi, nullptr, C, blockIdx.x, blockIdx.y);
}

__global__ void __launch_bounds__(256, 1)
o_gemm(const float* A, const float* BT, const float* bias,
       const float* res, float* C)
{
    extern __shared__ char smem[];
    gemm_body<false, false>(smem, A, BT, bias, res, C, blockIdx.x, blockIdx.y);
}

// ------------ fused weight transpose (+tf32 round): 2 weights per launch ----
__global__ void trans2_kernel(const float* __restrict__ s0, float* __restrict__ d0,
                              const float* __restrict__ s1, float* __restrict__ d1)
{
    __shared__ float t[32][33];
    const float* src = blockIdx.z ? s1 : s0;
    float* dst = blockIdx.z ? d1 : d0;
    int x = blockIdx.x * 32 + threadIdx.x;
    int y0 = blockIdx.y * 32;
    #pragma unroll
    for (int i = threadIdx.y; i < 32; i += 8)
        t[i][threadIdx.x] = src[(size_t)(y0 + i) * HH + x];
    __syncthreads();
    int xo = blockIdx.y * 32 + threadIdx.x;
    int yo0 = blockIdx.x * 32;
    #pragma unroll
    for (int i = threadIdx.y; i < 32; i += 8)
        dst[(size_t)(yo0 + i) * HH + xo] = f2tf_f(t[threadIdx.x][i]);
}

// ---------------- per-(b,h) V transpose: VT[b][h][d][s] = V[b][s][h*64+d] ---
__global__ void vtrans_kernel(const float* __restrict__ V, float* __restrict__ VT)
{
    __shared__ float t[32][33];
    int bh = blockIdx.z;
    int s0 = blockIdx.x * 32, d0 = blockIdx.y * 32;
    int b = bh >> 4, h = bh & 15;
    const float* src = V + ((size_t)b * SS + s0) * HH + h * HDD + d0;
    #pragma unroll
    for (int i = threadIdx.y; i < 32; i += 8)
        t[i][threadIdx.x] = src[(size_t)i * HH + threadIdx.x];
    __syncthreads();
    float* dst = VT + ((size_t)bh * HDD + d0) * SS + s0;
    #pragma unroll
    for (int i = threadIdx.y; i < 32; i += 8)
        dst[(size_t)i * SS + threadIdx.x] = t[threadIdx.x][i];
}

// ---------------- stage 1 of query mean over seq -------
__global__ void qmean_part(const float* __restrict__ q)
{
    int b = blockIdx.y, ch = blockIdx.x;
    int tid = threadIdx.x;
    for (int c = tid; c < HH; c += 256) {
        const float* base = q + ((size_t)b * SS + ch * 64) * HH + c;
        float s = 0.f;
        #pragma unroll 4
        for (int r = 0; r < 64; r++) s += base[(size_t)r * HH];
        g_part[((size_t)b * 16 + ch) * HH + c] = s;
    }
}

// -------- spec MLP layer 1 partials: grid(8, BB), 512 threads --------------
// block handles 128 rows of Ws1 [1024,512]; partial over those rows per col.
__global__ void spec1_kernel(const float* __restrict__ Ws1)
{
    __shared__ float sin_s[128];
    int b = blockIdx.y, ch = blockIdx.x;
    int tid = threadIdx.x;          // 512
    int r0 = ch * 128;
    if (tid < 128) {
        float s = 0.f;
        #pragma unroll
        for (int p = 0; p < 16; p++) s += g_part[((size_t)b * 16 + p) * HH + r0 + tid];
        sin_s[tid] = s * (1.0f / SS);
    }
    __syncthreads();
    float acc = 0.f;
    #pragma unroll 4
    for (int j = 0; j < 128; j++)
        acc += sin_s[j] * Ws1[(size_t)(r0 + j) * 512 + tid];
    g_h1p[((size_t)b * 8 + ch) * 512 + tid] = acc;
}

// -------- spec MLP layer 2 + sigmoid-mean: grid(BB), 512 threads -----------
__global__ void spec2_kernel(const float* __restrict__ bs1,
                             const float* __restrict__ Ws2,
                             const float* __restrict__ bs2)
{
    __shared__ float h1[512];
    __shared__ float red[512];
    int b = blockIdx.x, tid = threadIdx.x;
    {
        float s = bs1[tid];
        #pragma unroll
        for (int ch = 0; ch < 8; ch++) s += g_h1p[((size_t)b * 8 + ch) * 512 + tid];
        h1[tid] = fmaxf(s, 0.f);
    }
    __syncthreads();
    float a0 = bs2[tid], a1 = bs2[tid + 512];
    for (int i = 0; i < 512; i++) {
        float hv = h1[i];
        a0 += hv * Ws2[(size_t)i * HH + tid];
        a1 += hv * Ws2[(size_t)i * HH + tid + 512];
    }
    float acc = 1.0f / (1.0f + __expf(-a0)) + 1.0f / (1.0f + __expf(-a1));
    red[tid] = acc;
    __syncthreads();
    for (int off = 256; off > 0; off >>= 1) {
        if (tid < off) red[tid] += red[tid + off];
        __syncthreads();
    }
    if (tid == 0) g_spec[b] = red[0] * (1.0f / HH);
}

// ================  tensor-core flash attention  =============================
// CTA: 128 q-rows of one (b,h). 8 warps, 16 q-rows each (full 64-key width).
// All operands pre-rounded to tf32 -> no cvts in the hot loop.
#define ASTR 272                       // bytes per smem row (68 floats)
#define AQ_OFF 0                       // Q: 128 rows
#define AK_OFF (AQ_OFF + 128*ASTR)     // K: 64 rows
#define AV_OFF (AK_OFF + 64*ASTR)      // VT: 64 rows (d-major)
#define AP_OFF (AV_OFF + 64*ASTR)      // P: 128 rows
#define A_SMEM (AP_OFF + 128*ASTR)     // 104448 bytes

__global__ void __launch_bounds__(256, 2)
attn_mma(const float* __restrict__ msb)
{
    extern __shared__ char smem[];
    __shared__ float red[256];
    __shared__ float mh_s;
    uint32_t sb = smem_u32(smem);
    const int tid = threadIdx.x;
    const int lane = tid & 31;
    const int w = tid >> 5;
    const int b = blockIdx.z, h = blockIdx.y, q0 = blockIdx.x << 7;

    const uint32_t Qa = sb + AQ_OFF + (uint32_t)((16 * w + (lane & 15)) * ASTR + (lane >> 4) * 16);
    const uint32_t Pa = sb + AP_OFF + (uint32_t)((16 * w + (lane & 15)) * ASTR + (lane >> 4) * 16);
    const uint32_t Kb = sb + AK_OFF + (uint32_t)(((((lane >> 4) << 3) + (lane & 7)) * ASTR) + ((lane >> 3) & 1) * 16);
    const uint32_t Vb = sb + AV_OFF + (uint32_t)(((((lane >> 4) << 3) + (lane & 7)) * ASTR) + ((lane >> 3) & 1) * 16);

    // load Q tile (128 x 64)
    {
        const float* Qg = g_Q + ((size_t)b * SS + q0) * HH + h * HDD;
        #pragma unroll
        for (int i = 0; i < 8; i++) {
            int f = tid + i * 256;
            int r = f >> 4, c4 = f & 15;
            cp16(sb + AQ_OFF + (uint32_t)(r * ASTR + c4 * 16),
                 Qg + (size_t)r * HH + c4 * 4);
        }
        CP_COMMIT();
    }

    // per-head msb mean (block reduce, overlaps Q load)
    {
        const float* p = msb + (size_t)h * HDD * HDD;
        float s = 0.f;
        for (int i = tid; i < HDD * HDD; i += 256) s += p[i];
        red[tid] = s;
        __syncthreads();
        for (int off = 128; off > 0; off >>= 1) {
            if (tid < off) red[tid] += red[tid + off];
            __syncthreads();
        }
        if (tid == 0) mh_s = red[0] * (1.0f / (HDD * HDD));
        __syncthreads();
    }

    const float mh = mh_s;
    const float sp = g_spec[b];

    float oacc[8][4] = {};
    float m0 = -1e30f, m1 = -1e30f, l0 = 0.f, l1 = 0.f;

    for (int kt = 0; kt < 16; kt++) {
        __syncthreads();
        {
            const float* Kg = g_K + ((size_t)b * SS + kt * 64) * HH + h * HDD;
            const float* Vg = g_VT + (size_t)(b * NHH + h) * HDD * SS + kt * 64;
            #pragma unroll
            for (int i = 0; i < 4; i++) {
                int f = tid + i * 256;
                int r = f >> 4, c4 = f & 15;
                cp16(sb + AK_OFF + (uint32_t)(r * ASTR + c4 * 16),
                     Kg + (size_t)r * HH + c4 * 4);
                cp16(sb + AV_OFF + (uint32_t)(r * ASTR + c4 * 16),
                     Vg + (size_t)r * SS + c4 * 4);
            }
            CP_COMMIT();
        }
        CP_WAIT0();
        __syncthreads();

        // ---- S = Q @ K^T ----
        float sacc[8][4] = {};
        #pragma unroll
        for (int ks = 0; ks < 8; ks++) {
            uint32_t a[4];
            ldsm4(a, Qa + ks * 32);
            #pragma unroll
            for (int kb = 0; kb < 4; kb++) {
                uint32_t bb[4];
                ldsm4(bb, Kb + kb * 16 * ASTR + ks * 32);
                mma8(sacc[2 * kb],     a, bb);
                mma8(sacc[2 * kb + 1], a, bb + 2);
            }
        }

        // ---- gate + online softmax ----
        float tm0 = -1e30f, tm1 = -1e30f;
        #pragma unroll
        for (int nf = 0; nf < 8; nf++) {
            #pragma unroll
            for (int j = 0; j < 4; j++) {
                float s0 = sacc[nf][j] * SCALE_C;
                float e = 1.0f / (1.0f + __expf(-s0 * mh));
                float p = s0 * (1.0f + e * SP_C) * sp;
                sacc[nf][j] = p;
                if (j < 2) tm0 = fmaxf(tm0, p); else tm1 = fmaxf(tm1, p);
            }
        }
        tm0 = fmaxf(tm0, __shfl_xor_sync(0xffffffff, tm0, 1));
        tm0 = fmaxf(tm0, __shfl_xor_sync(0xffffffff, tm0, 2));
        tm1 = fmaxf(tm1, __shfl_xor_sync(0xffffffff, tm1, 1));
        tm1 = fmaxf(tm1, __shfl_xor_sync(0xffffffff, tm1, 2));

        float nm0 = fmaxf(m0, tm0), nm1 = fmaxf(m1, tm1);
        float sc0 = __expf(m0 - nm0), sc1 = __expf(m1 - nm1);
        float su0 = 0.f, su1 = 0.f;
        #pragma unroll
        for (int nf = 0; nf < 8; nf++) {
            float p0 = __expf(sacc[nf][0] - nm0);
            float p1 = __expf(sacc[nf][1] - nm0);
            float p2 = __expf(sacc[nf][2] - nm1);
            float p3 = __expf(sacc[nf][3] - nm1);
            su0 += p0 + p1; su1 += p2 + p3;
            sacc[nf][0] = p0; sacc[nf][1] = p1;
            sacc[nf][2] = p2; sacc[nf][3] = p3;
        }
        su0 += __shfl_xor_sync(0xffffffff, su0, 1);
        su0 += __shfl_xor_sync(0xffffffff, su0, 2);
        su1 += __shfl_xor_sync(0xffffffff, su1, 1);
        su1 += __shfl_xor_sync(0xffffffff, su1, 2);
        l0 = l0 * sc0 + su0;
        l1 = l1 * sc1 + su1;
        m0 = nm0; m1 = nm1;

        #pragma unroll
        for (int nf = 0; nf < 8; nf++) {
            oacc[nf][0] *= sc0; oacc[nf][1] *= sc0;
            oacc[nf][2] *= sc1; oacc[nf][3] *= sc1;
        }

        // ---- write P (tf32-rounded) to smem ----
        {
            int r0 = 16 * w + (lane >> 2);
            uint32_t p0a = (uint32_t)(AP_OFF + r0 * ASTR + 2 * (lane & 3) * 4);
            #pragma unroll
            for (int nf = 0; nf < 8; nf++) {
                float2 v0 = make_float2(f2tf_f(sacc[nf][0]), f2tf_f(sacc[nf][1]));
                float2 v1 = make_float2(f2tf_f(sacc[nf][2]), f2tf_f(sacc[nf][3]));
                *(float2*)(smem + p0a + nf * 32) = v0;
                *(float2*)(smem + p0a + 8 * ASTR + nf * 32) = v1;
            }
        }
        __syncwarp();

        // ---- O += P @ V ----
        #pragma unroll
        for (int ks = 0; ks < 8; ks++) {
            uint32_t a[4];
            ldsm4(a, Pa + ks * 32);
            #pragma unroll
            for (int db = 0; db < 4; db++) {
                uint32_t bb[4];
                ldsm4(bb, Vb + db * 16 * ASTR + ks * 32);
                mma8(oacc[2 * db],     a, bb);
                mma8(oacc[2 * db + 1], a, bb + 2);
            }
        }
    }

    // ---- epilogue: normalize + store ctx (tf32-rounded: feeds O-proj mma) --
    float inv0 = 1.0f / l0, inv1 = 1.0f / l1;
    float* Og = g_ctx + ((size_t)b * SS + q0) * HH + h * HDD;
    int r0 = 16 * w + (lane >> 2);
    #pragma unroll
    for (int nf = 0; nf < 8; nf++) {
        int c = 8 * nf + 2 * (lane & 3);
        *(float2*)&Og[(size_t)r0 * HH + c] =
            make_float2(f2tf_f(oacc[nf][0] * inv0), f2tf_f(oacc[nf][1] * inv0));
        *(float2*)&Og[(size_t)(r0 + 8) * HH + c] =
            make_float2(f2tf_f(oacc[nf][2] * inv1), f2tf_f(oacc[nf][3] * inv1));
    }
}

// ---------------- row LayerNorm ----------------
__global__ void ln_kernel(const float* __restrict__ x,
                          const float* __restrict__ g,
                          const float* __restrict__ bta,
                          float* __restrict__ out)
{
    __shared__ float r1[256];
    __shared__ float r2[256];
    int row = blockIdx.x, tid = threadIdx.x;
    const float4* xr = (const float4*)(x + (size_t)row * HH);
    float4 a = xr[tid];
    float s = a.x + a.y + a.z + a.w;
    float ss = a.x * a.x + a.y * a.y + a.z * a.z + a.w * a.w;
    r1[tid] = s; r2[tid] = ss;
    __syncthreads();
    for (int off = 128; off > 0; off >>= 1) {
        if (tid < off) { r1[tid] += r1[tid + off]; r2[tid] += r2[tid + off]; }
        __syncthreads();
    }
    float mu = r1[0] * (1.0f / HH);
    float var = r2[0] * (1.0f / HH) - mu * mu;
    float rstd = rsqrtf(var + EPS_C);
    float4 gg = ((const float4*)g)[tid];
    float4 bb = ((const float4*)bta)[tid];
    float4 o;
    o.x = (a.x - mu) * rstd * gg.x + bb.x;
    o.y = (a.y - mu) * rstd * gg.y + bb.y;
    o.z = (a.z - mu) * rstd * gg.z + bb.z;
    o.w = (a.w - mu) * rstd * gg.w + bb.w;
    ((float4*)(out + (size_t)row * HH))[tid] = o;
}

// ---------------- launch ----------------
extern "C" void kernel_launch(void* const* d_in, const int* in_sizes, int n_in,
                              void* d_out, int out_size)
{
    const float* query = (const float*)d_in[0];
    const float* key_t = (const float*)d_in[1];
    const float* value = (const float*)d_in[2];
    const float* Wq = (const float*)d_in[3];
    const float* bq = (const float*)d_in[4];
    const float* Wk = (const float*)d_in[5];
    const float* bk = (const float*)d_in[6];
    const float* Wv = (const float*)d_in[7];
    const float* bv = (const float*)d_in[8];
    const float* msb = (const float*)d_in[9];
    const float* Ws1 = (const float*)d_in[10];
    const float* bs1 = (const float*)d_in[11];
    const float* Ws2 = (const float*)d_in[12];
    const float* bs2 = (const float*)d_in[13];
    const float* Wo = (const float*)d_in[14];
    const float* bo = (const float*)d_in[15];
    const float* ln_g = (const float*)d_in[16];
    const float* ln_b = (const float*)d_in[17];

    float *pQ, *pK, *pV, *pVT, *pCtx, *pPre, *pWT;
    cudaGetSymbolAddress((void**)&pQ, g_Q);
    cudaGetSymbolAddress((void**)&pK, g_K);
    cudaGetSymbolAddress((void**)&pV, g_V);
    cudaGetSymbolAddress((void**)&pVT, g_VT);
    cudaGetSymbolAddress((void**)&pCtx, g_ctx);
    cudaGetSymbolAddress((void**)&pPre, g_pre);
    cudaGetSymbolAddress((void**)&pWT, g_WT);

    float* WTq = pWT + 0 * HH * HH;
    float* WTk = pWT + 1 * HH * HH;
    float* WTv = pWT + 2 * HH * HH;
    float* WTo = pWT + 3 * HH * HH;

    cudaFuncSetAttribute(qkv_gemm, cudaFuncAttributeMaxDynamicSharedMemorySize,
                         GSM_TOTAL);
    cudaFuncSetAttribute(o_gemm, cudaFuncAttributeMaxDynamicSharedMemorySize,
                         GSM_TOTAL);
    cudaFuncSetAttribute(attn_mma, cudaFuncAttributeMaxDynamicSharedMemorySize,
                         A_SMEM);

    dim3 tb(32, 8);
    dim3 tg2(32, 32, 2);

    // 0-1: weight transposes (+tf32 rounding)
    trans2_kernel<<<tg2, tb>>>(Wq, WTq, Wk, WTk);
    trans2_kernel<<<tg2, tb>>>(Wv, WTv, Wo, WTo);
    // 2-4: spec MLP chain (independent of GEMMs)
    qmean_part<<<dim3(16, BB), 256>>>(query);
    spec1_kernel<<<dim3(8, BB), 512>>>(Ws1);
    spec2_kernel<<<BB, 512>>>(bs1, Ws2, bs2);
    // 5 (ncu -s 5 profiles this): fused Q/K/V projection GEMM
    qkv_gemm<<<dim3(GN / 128, M_TOT / 128, 3), 256, GSM_TOTAL>>>(
        query, key_t, value, WTq, WTk, WTv, bq, bk, bv, pQ, pK, pV);
    // 6: V transpose for attention B-operand
    vtrans_kernel<<<dim3(SS / 32, HDD / 32, BB * NHH), tb>>>(pV, pVT);
    // 7: tensor-core flash attention (msb mean fused into prologue)
    attn_mma<<<dim3(SS / 128, NHH, BB), 256, A_SMEM>>>(msb);
    // 8: output projection + bias + residual
    o_gemm<<<dim3(GN / 128, M_TOT / 128), 256, GSM_TOTAL>>>(pCtx, WTo, bo, query, pPre);
    // 9: LayerNorm -> d_out
    ln_kernel<<<M_TOT, 256>>>(pPre, ln_g, ln_b, (float*)d_out);
}